// round 15
// baseline (speedup 1.0000x reference)
#include <cuda_runtime.h>
#include <math.h>
#include <stdint.h>

#define NEXP    8
#define HDIM    4096
#define TOK     4
#define WARPS   16
#define THREADS 512
#define NTOK    16384            // 4 * 4096 tokens
#define NGROUP  (NTOK / TOK)     // 4096 warp-groups
#define H4      (HDIM / 4)       // 1024 float4 per row
#define KSUPER  16               // superiterations (2 k-iters each)
#define NSLOT   3

#define ROW_B    1024                          // 1 KB contiguous per token row
#define SLOT_B   (TOK * ROW_B)                 // 4 KB per slot (2 k-iters)
#define WBUF_B   (NSLOT * SLOT_B)              // 12 KB per warp
#define SMEM_B   (WARPS * WBUF_B)              // 192 KB (weights via L1)

// ---- cp.async primitives (16B, .cg = L1-bypass; keeps L1 for weights) ----
#define CP_ASYNC16(dst, src) \
    asm volatile("cp.async.cg.shared.global [%0], [%1], 16;" \
                 :: "r"(dst), "l"(src) : "memory")
#define CP_COMMIT() asm volatile("cp.async.commit_group;" ::: "memory")
#define CP_WAIT2()  asm volatile("cp.async.wait_group 2;"  ::: "memory")

__global__ __launch_bounds__(THREADS, 1)
void moe_router_kernel(const float* __restrict__ hs,
                       const float* __restrict__ rw,
                       float* __restrict__ out)
{
    extern __shared__ float sm[];            // hidden ring buffers only

    const int lane = threadIdx.x & 31;
    const int wid  = threadIdx.x >> 5;

    const uint32_t smb = (uint32_t)__cvta_generic_to_shared(sm);
    const uint32_t hb  = smb + wid * WBUF_B;
    const float4*  hgen = reinterpret_cast<const float4*>(
        reinterpret_cast<const char*>(sm) + wid * WBUF_B);

    const int gwarp = blockIdx.x * WARPS + wid;
    const int nwarp = gridDim.x * WARPS;

    const float4* rw4 = reinterpret_cast<const float4*>(rw);

    float* out_w = out;                     // [NTOK, 2] top-k weights
    float* out_i = out + (size_t)NTOK * 2;  // [NTOK, 2] indices (as float)
    float* out_l = out + (size_t)NTOK * 4;  // [NTOK, 8] raw logits

    for (int g = gwarp; g < NGROUP; g += nwarp) {
        const size_t t0 = (size_t)g * TOK;
        const float* hsrow = hs + t0 * HDIM;

        float v[TOK * NEXP];
        #pragma unroll
        for (int x = 0; x < TOK * NEXP; x++) v[x] = 0.0f;

        // Prologue: fill slots 0..2 = superiters 0..2.
        // Per slot: token-major issue -> 1 KB CONTIGUOUS burst per row.
        #pragma unroll
        for (int s = 0; s < NSLOT; s++) {
            #pragma unroll
            for (int t = 0; t < TOK; t++)
                #pragma unroll
                for (int c = 0; c < 2; c++)
                    CP_ASYNC16(hb + s * SLOT_B + t * ROW_B + c * 512 + lane * 16,
                               hsrow + (size_t)t * HDIM + ((s * 2 + c) * 32 + lane) * 4);
            CP_COMMIT();
        }

        uint32_t slotoff = 0;
        #pragma unroll 1
        for (int si = 0; si < KSUPER; si++) {
            CP_WAIT2();                      // superiter si's slot complete

            // Read BOTH k-iters of the slot into registers before refill
            float4 h[2][TOK];
            #pragma unroll
            for (int t = 0; t < TOK; t++) {
                h[0][t] = hgen[(slotoff >> 4) + t * (ROW_B / 16) + lane];
                h[1][t] = hgen[(slotoff >> 4) + t * (ROW_B / 16) + 32 + lane];
            }

            // Refill this slot for superiter si+NSLOT (1 KB bursts per row)
            if (si + NSLOT < KSUPER) {
                const int sf = si + NSLOT;
                #pragma unroll
                for (int t = 0; t < TOK; t++)
                    #pragma unroll
                    for (int c = 0; c < 2; c++)
                        CP_ASYNC16(hb + slotoff + t * ROW_B + c * 512 + lane * 16,
                                   hsrow + (size_t)t * HDIM + ((sf * 2 + c) * 32 + lane) * 4);
            }
            CP_COMMIT();                     // exact group counting

            // Two k-iterations of FMAs (weights from L1; 128 KB resident)
            #pragma unroll
            for (int c = 0; c < 2; c++) {
                const int kk = (si * 2 + c) * 32 + lane;
                float4 w[NEXP];
                #pragma unroll
                for (int e = 0; e < NEXP; e++)
                    w[e] = __ldg(&rw4[e * H4 + kk]);

                #pragma unroll
                for (int t = 0; t < TOK; t++) {
                    const float4 hh = h[c][t];
                    #pragma unroll
                    for (int e = 0; e < NEXP; e++) {
                        v[t * NEXP + e] = fmaf(hh.x, w[e].x, v[t * NEXP + e]);
                        v[t * NEXP + e] = fmaf(hh.y, w[e].y, v[t * NEXP + e]);
                        v[t * NEXP + e] = fmaf(hh.z, w[e].z, v[t * NEXP + e]);
                        v[t * NEXP + e] = fmaf(hh.w, w[e].w, v[t * NEXP + e]);
                    }
                }
            }

            slotoff = (slotoff == (NSLOT - 1) * SLOT_B) ? 0u : slotoff + SLOT_B;
        }

        // Tree-exchange reduction: 31 SHFL; lane L ends with value index L=t*8+e
        #pragma unroll
        for (int o = 16; o >= 1; o >>= 1) {
            const bool up = (lane & o) != 0;
            #pragma unroll
            for (int j = 0; j < o; j++) {
                const float give = up ? v[j] : v[j + o];
                const float keep = up ? v[j + o] : v[j];
                const float recv = __shfl_xor_sync(0xffffffffu, give, o);
                v[j] = keep + recv;
            }
        }

        const float logit = v[0];       // logit[token = lane>>3][expert = lane&7]
        const int   sub   = lane & 7;

        // Coalesced logit store: 32 consecutive floats per warp
        out_l[t0 * NEXP + lane] = logit;

        // Top-1 within each 8-lane token group (ties -> lowest expert index)
        float bv = logit; int bi = sub;
        #pragma unroll
        for (int o = 4; o >= 1; o >>= 1) {
            const float ov = __shfl_xor_sync(0xffffffffu, bv, o);
            const int   oi = __shfl_xor_sync(0xffffffffu, bi, o);
            if (ov > bv || (ov == bv && oi < bi)) { bv = ov; bi = oi; }
        }
        // Top-2: exclude the winner, reduce again
        float sv = (sub == bi) ? -INFINITY : logit; int si2 = sub;
        #pragma unroll
        for (int o = 4; o >= 1; o >>= 1) {
            const float ov = __shfl_xor_sync(0xffffffffu, sv, o);
            const int   oi = __shfl_xor_sync(0xffffffffu, si2, o);
            if (ov > sv || (ov == sv && oi < si2)) { sv = ov; si2 = oi; }
        }

        if (sub == 0) {
            const size_t tok = t0 + (lane >> 3);
            // renormalized top-2 softmax weights
            const float e2 = __expf(sv - bv);
            const float r  = 1.0f / (1.0f + e2);
            out_w[tok * 2 + 0] = r;
            out_w[tok * 2 + 1] = e2 * r;
            out_i[tok * 2 + 0] = (float)bi;
            out_i[tok * 2 + 1] = (float)si2;
        }
    }
}

extern "C" void kernel_launch(void* const* d_in, const int* in_sizes, int n_in,
                              void* d_out, int out_size)
{
    const float* hs = (const float*)d_in[0];   // hidden_states [4,4096,4096] f32
    const float* rw = (const float*)d_in[1];   // router_weight [8,4096] f32
    float* out = (float*)d_out;

    (void)in_sizes; (void)n_in; (void)out_size;

    cudaFuncSetAttribute(moe_router_kernel,
                         cudaFuncAttributeMaxDynamicSharedMemorySize, SMEM_B);

    moe_router_kernel<<<152, THREADS, SMEM_B>>>(hs, rw, out);
}

// round 16
// speedup vs baseline: 1.0203x; 1.0203x over previous
#include <cuda_runtime.h>
#include <math.h>
#include <stdint.h>

#define NEXP     8
#define HDIM     4096
#define WARPS    20
#define THREADS  640
#define BLOCKS   152
#define NWARP    (BLOCKS * WARPS)     // 3040
#define NTOK     16384
#define H4       (HDIM / 4)           // 1024 float4 per row
#define KITERS   (H4 / 32)            // 32 k-iterations
#define NSLOT    3
// one group per warp: first RBIG warps own 6 tokens, rest own 5
#define TOK_BIG   6
#define TOK_SMALL 5
#define RBIG      (NTOK - TOK_SMALL * NWARP)   // 1184

#define SLOT_B   (TOK_BIG * 512)               // 3072 B per slot (sized for 6)
#define WBUF_B   (NSLOT * SLOT_B)              // 9216 B per warp
#define SMEM_B   (WARPS * WBUF_B)              // 180 KB (weights via L1)

// ---- cp.async primitives (16B, .cg = L1-bypass; keeps L1 for weights) ----
#define CP_ASYNC16(dst, src) \
    asm volatile("cp.async.cg.shared.global [%0], [%1], 16;" \
                 :: "r"(dst), "l"(src) : "memory")
#define CP_COMMIT() asm volatile("cp.async.commit_group;" ::: "memory")
#define CP_WAIT2()  asm volatile("cp.async.wait_group 2;"  ::: "memory")

template<int TOKN>
__device__ __forceinline__ void process_warp(size_t t0, int lane,
                                             uint32_t hb, const float4* hgen,
                                             const float* __restrict__ hs,
                                             const float4* __restrict__ rw4,
                                             float* __restrict__ out_w,
                                             float* __restrict__ out_i,
                                             float* __restrict__ out_l)
{
    const float* hsrow = hs + t0 * HDIM;

    float acc[TOKN][NEXP];
    #pragma unroll
    for (int t = 0; t < TOKN; t++)
        #pragma unroll
        for (int e = 0; e < NEXP; e++)
            acc[t][e] = 0.0f;

    // Prologue: async-fill slots 0,1,2 (iters 0,1,2); one 16B per lane per row
    #pragma unroll
    for (int s = 0; s < NSLOT; s++) {
        #pragma unroll
        for (int t = 0; t < TOKN; t++)
            CP_ASYNC16(hb + s * SLOT_B + t * 512 + lane * 16,
                       hsrow + (size_t)t * HDIM + (s * 32 + lane) * 4);
        CP_COMMIT();
    }

    uint32_t slotoff = 0;
    #pragma unroll 1
    for (int i = 0; i < KITERS; i++) {
        CP_WAIT2();                          // iter i's slot complete

        // weights straight from L1 (128 KB resident; hidden bypasses L1)
        const int kk = i * 32 + lane;
        float4 w[NEXP];
        #pragma unroll
        for (int e = 0; e < NEXP; e++)
            w[e] = __ldg(&rw4[e * H4 + kk]);

        const bool refill = (i + NSLOT < KITERS);
        const int  kf     = (i + NSLOT) * 32 + lane;

        // Per token row: read row -> refill row -> FMA (read-before-refill)
        #pragma unroll
        for (int t = 0; t < TOKN; t++) {
            const float4 h = hgen[(slotoff >> 4) + t * 32 + lane];
            if (refill)
                CP_ASYNC16(hb + slotoff + t * 512 + lane * 16,
                           hsrow + (size_t)t * HDIM + kf * 4);
            #pragma unroll
            for (int e = 0; e < NEXP; e++) {
                acc[t][e] = fmaf(h.x, w[e].x, acc[t][e]);
                acc[t][e] = fmaf(h.y, w[e].y, acc[t][e]);
                acc[t][e] = fmaf(h.z, w[e].z, acc[t][e]);
                acc[t][e] = fmaf(h.w, w[e].w, acc[t][e]);
            }
        }
        CP_COMMIT();                         // exact group counting

        slotoff = (slotoff == (NSLOT - 1) * SLOT_B) ? 0u : slotoff + SLOT_B;
    }

    // Butterfly reduction (once per warp per kernel — amortized)
    #pragma unroll
    for (int off = 16; off > 0; off >>= 1) {
        #pragma unroll
        for (int t = 0; t < TOKN; t++)
            #pragma unroll
            for (int e = 0; e < NEXP; e++)
                acc[t][e] += __shfl_xor_sync(0xffffffffu, acc[t][e], off);
    }

    // Lanes 0..TOKN-1: one token each — top-2 + renorm + writes
    if (lane < TOKN) {
        float l[NEXP];
        #pragma unroll
        for (int t = 0; t < TOKN; t++) {
            if (lane == t) {
                #pragma unroll
                for (int e = 0; e < NEXP; e++) l[e] = acc[t][e];
            }
        }

        const size_t tok = t0 + lane;

        // argmax (ties -> lowest index, matching jax.lax.top_k)
        int   i1 = 0; float v1 = l[0];
        #pragma unroll
        for (int e = 1; e < NEXP; e++)
            if (l[e] > v1) { v1 = l[e]; i1 = e; }
        int   i2 = -1; float v2 = -INFINITY;
        #pragma unroll
        for (int e = 0; e < NEXP; e++)
            if (e != i1 && l[e] > v2) { v2 = l[e]; i2 = e; }

        // renormalized top-2 softmax weights
        const float e2 = __expf(v2 - v1);
        const float r  = 1.0f / (1.0f + e2);

        out_w[tok * 2 + 0] = r;
        out_w[tok * 2 + 1] = e2 * r;
        out_i[tok * 2 + 0] = (float)i1;
        out_i[tok * 2 + 1] = (float)i2;
        #pragma unroll
        for (int e = 0; e < NEXP; e++)
            out_l[tok * NEXP + e] = l[e];
    }
}

__global__ __launch_bounds__(THREADS, 1)
void moe_router_kernel(const float* __restrict__ hs,
                       const float* __restrict__ rw,
                       float* __restrict__ out)
{
    extern __shared__ float sm[];            // hidden ring buffers only

    const int lane = threadIdx.x & 31;
    const int wid  = threadIdx.x >> 5;

    const uint32_t smb = (uint32_t)__cvta_generic_to_shared(sm);
    const uint32_t hb  = smb + wid * WBUF_B;
    const float4*  hgen = reinterpret_cast<const float4*>(
        reinterpret_cast<const char*>(sm) + wid * WBUF_B);

    // Interleaved mapping: 6-token warps spread across all SMs
    const int gwarp = wid * gridDim.x + blockIdx.x;

    const float4* rw4 = reinterpret_cast<const float4*>(rw);

    float* out_w = out;                     // [NTOK, 2] top-k weights
    float* out_i = out + (size_t)NTOK * 2;  // [NTOK, 2] indices (as float)
    float* out_l = out + (size_t)NTOK * 4;  // [NTOK, 8] raw logits

    // One group per warp: warps [0, RBIG) own 6 tokens, the rest own 5.
    if (gwarp < RBIG) {
        const size_t t0 = (size_t)gwarp * TOK_BIG;
        process_warp<TOK_BIG>(t0, lane, hb, hgen, hs, rw4, out_w, out_i, out_l);
    } else {
        const size_t t0 = (size_t)RBIG * TOK_BIG
                        + (size_t)(gwarp - RBIG) * TOK_SMALL;
        process_warp<TOK_SMALL>(t0, lane, hb, hgen, hs, rw4, out_w, out_i, out_l);
    }
}

extern "C" void kernel_launch(void* const* d_in, const int* in_sizes, int n_in,
                              void* d_out, int out_size)
{
    const float* hs = (const float*)d_in[0];   // hidden_states [4,4096,4096] f32
    const float* rw = (const float*)d_in[1];   // router_weight [8,4096] f32
    float* out = (float*)d_out;

    (void)in_sizes; (void)n_in; (void)out_size;

    cudaFuncSetAttribute(moe_router_kernel,
                         cudaFuncAttributeMaxDynamicSharedMemorySize, SMEM_B);

    moe_router_kernel<<<BLOCKS, THREADS, SMEM_B>>>(hs, rw, out);
}

// round 17
// speedup vs baseline: 1.3748x; 1.3474x over previous
#include <cuda_runtime.h>
#include <math.h>
#include <stdint.h>

#define NEXP    8
#define HDIM    4096
#define TOK     4
#define WARPS   16
#define THREADS 512
#define NTOK    16384            // 4 * 4096 tokens
#define NGROUP  (NTOK / TOK)     // 4096 warp-groups
#define H4      (HDIM / 4)       // 1024 float4 per row
#define KITERS  (H4 / 32)        // 32 k-iterations per group
#define NSLOT   3

#define SW_BYTES (NEXP * HDIM * 4)                // 128 KB weights
#define SLOT_B   (TOK * 512)                      // 2 KB per slot
#define WBUF_B   (NSLOT * SLOT_B)                 // 6 KB per warp (3 slots)
#define SMEM_B   (SW_BYTES + WARPS * WBUF_B)      // 224 KB total

// ---- cp.async primitives (16B, L1-bypass) ----
#define CP_ASYNC16(dst, src) \
    asm volatile("cp.async.cg.shared.global [%0], [%1], 16;" \
                 :: "r"(dst), "l"(src) : "memory")
#define CP_COMMIT() asm volatile("cp.async.commit_group;" ::: "memory")
#define CP_WAIT2()  asm volatile("cp.async.wait_group 2;"  ::: "memory")

// One k-iteration with a COMPILE-TIME slot: all smem addresses are immediates.
template<int SLOT>
__device__ __forceinline__ void do_iter(int i, int lane,
                                        const float* __restrict__ hsrow,
                                        const float4* __restrict__ sw4,
                                        uint32_t hb, const float4* hgen,
                                        float (&v)[TOK * NEXP])
{
    CP_WAIT2();                              // iter i's group complete

    const int kk = i * 32 + lane;
    float4 w[NEXP];
    #pragma unroll
    for (int e = 0; e < NEXP; e++)
        w[e] = sw4[e * H4 + kk];

    float4 h[TOK];
    #pragma unroll
    for (int t = 0; t < TOK; t++)
        h[t] = hgen[SLOT * (SLOT_B / 16) + t * 32 + lane];

    // Refill this slot for iter i+NSLOT (read-before-refill preserved)
    if (i + NSLOT < KITERS) {
        const int kf = (i + NSLOT) * 32 + lane;
        #pragma unroll
        for (int t = 0; t < TOK; t++)
            CP_ASYNC16(hb + SLOT * SLOT_B + t * 512 + lane * 16,
                       hsrow + (size_t)t * HDIM + kf * 4);
    }
    CP_COMMIT();                             // exact group counting

    #pragma unroll
    for (int t = 0; t < TOK; t++) {
        #pragma unroll
        for (int e = 0; e < NEXP; e++) {
            v[t * NEXP + e] = fmaf(h[t].x, w[e].x, v[t * NEXP + e]);
            v[t * NEXP + e] = fmaf(h[t].y, w[e].y, v[t * NEXP + e]);
            v[t * NEXP + e] = fmaf(h[t].z, w[e].z, v[t * NEXP + e]);
            v[t * NEXP + e] = fmaf(h[t].w, w[e].w, v[t * NEXP + e]);
        }
    }
}

__global__ __launch_bounds__(THREADS, 1)
void moe_router_kernel(const float* __restrict__ hs,
                       const float* __restrict__ rw,
                       float* __restrict__ out)
{
    extern __shared__ float sm[];
    float4* sw4 = reinterpret_cast<float4*>(sm);

    // Stage router weights into smem (coalesced, once per block)
    {
        const float4* rw4 = reinterpret_cast<const float4*>(rw);
        #pragma unroll
        for (int i = threadIdx.x; i < NEXP * H4; i += THREADS)
            sw4[i] = rw4[i];
    }
    __syncthreads();

    const int lane = threadIdx.x & 31;
    const int wid  = threadIdx.x >> 5;

    // This warp's private 3-slot hidden ring buffer
    const uint32_t smb = (uint32_t)__cvta_generic_to_shared(sm);
    const uint32_t hb  = smb + SW_BYTES + wid * WBUF_B;
    const float4*  hgen = reinterpret_cast<const float4*>(
        reinterpret_cast<const char*>(sm) + SW_BYTES + wid * WBUF_B);

    const int gwarp = blockIdx.x * WARPS + wid;
    const int nwarp = gridDim.x * WARPS;

    float* out_w = out;                     // [NTOK, 2] top-k weights
    float* out_i = out + (size_t)NTOK * 2;  // [NTOK, 2] indices (as float)
    float* out_l = out + (size_t)NTOK * 4;  // [NTOK, 8] raw logits

    for (int g = gwarp; g < NGROUP; g += nwarp) {
        const size_t t0 = (size_t)g * TOK;
        const float* hsrow = hs + t0 * HDIM;

        float v[TOK * NEXP];
        #pragma unroll
        for (int x = 0; x < TOK * NEXP; x++) v[x] = 0.0f;

        // Prologue: async-fill slots 0,1,2 (iters 0,1,2), one group each
        #pragma unroll
        for (int s = 0; s < NSLOT; s++) {
            #pragma unroll
            for (int t = 0; t < TOK; t++)
                CP_ASYNC16(hb + s * SLOT_B + t * 512 + lane * 16,
                           hsrow + (size_t)t * HDIM + (s * 32 + lane) * 4);
            CP_COMMIT();
        }

        // Mainloop: 10 rotations of 3 compile-time-slot stages (iters 0..29)
        #pragma unroll 1
        for (int i = 0; i < KITERS - 2; i += NSLOT) {
            do_iter<0>(i,     lane, hsrow, sw4, hb, hgen, v);
            do_iter<1>(i + 1, lane, hsrow, sw4, hb, hgen, v);
            do_iter<2>(i + 2, lane, hsrow, sw4, hb, hgen, v);
        }
        // Tail: iters 30 (slot 0), 31 (slot 1)
        do_iter<0>(KITERS - 2, lane, hsrow, sw4, hb, hgen, v);
        do_iter<1>(KITERS - 1, lane, hsrow, sw4, hb, hgen, v);

        // Tree-exchange reduction: 31 SHFL; lane L ends with value index L=t*8+e
        #pragma unroll
        for (int o = 16; o >= 1; o >>= 1) {
            const bool up = (lane & o) != 0;
            #pragma unroll
            for (int j = 0; j < o; j++) {
                const float give = up ? v[j] : v[j + o];
                const float keep = up ? v[j + o] : v[j];
                const float recv = __shfl_xor_sync(0xffffffffu, give, o);
                v[j] = keep + recv;
            }
        }

        const float logit = v[0];       // logit[token = lane>>3][expert = lane&7]
        const int   sub   = lane & 7;

        // Coalesced logit store: 32 consecutive floats per warp
        out_l[t0 * NEXP + lane] = logit;

        // Top-1 within each 8-lane token group (ties -> lowest expert index)
        float bv = logit; int bi = sub;
        #pragma unroll
        for (int o = 4; o >= 1; o >>= 1) {
            const float ov = __shfl_xor_sync(0xffffffffu, bv, o);
            const int   oi = __shfl_xor_sync(0xffffffffu, bi, o);
            if (ov > bv || (ov == bv && oi < bi)) { bv = ov; bi = oi; }
        }
        // Top-2: exclude the winner, reduce again
        float sv = (sub == bi) ? -INFINITY : logit; int si = sub;
        #pragma unroll
        for (int o = 4; o >= 1; o >>= 1) {
            const float ov = __shfl_xor_sync(0xffffffffu, sv, o);
            const int   oi = __shfl_xor_sync(0xffffffffu, si, o);
            if (ov > sv || (ov == sv && oi < si)) { sv = ov; si = oi; }
        }

        if (sub == 0) {
            const size_t tok = t0 + (lane >> 3);
            // renormalized top-2 softmax weights
            const float e2 = __expf(sv - bv);
            const float r  = 1.0f / (1.0f + e2);
            out_w[tok * 2 + 0] = r;
            out_w[tok * 2 + 1] = e2 * r;
            out_i[tok * 2 + 0] = (float)bi;
            out_i[tok * 2 + 1] = (float)si;
        }
    }
}

extern "C" void kernel_launch(void* const* d_in, const int* in_sizes, int n_in,
                              void* d_out, int out_size)
{
    const float* hs = (const float*)d_in[0];   // hidden_states [4,4096,4096] f32
    const float* rw = (const float*)d_in[1];   // router_weight [8,4096] f32
    float* out = (float*)d_out;

    (void)in_sizes; (void)n_in; (void)out_size;

    cudaFuncSetAttribute(moe_router_kernel,
                         cudaFuncAttributeMaxDynamicSharedMemorySize, SMEM_B);

    moe_router_kernel<<<152, THREADS, SMEM_B>>>(hs, rw, out);
}